// round 4
// baseline (speedup 1.0000x reference)
#include <cuda_runtime.h>
#include <math.h>
#include <stddef.h>

#define TT 512
#define BB 32
#define FF 1024
#define HH 256
#define NSTEP 64

// ---------------- scratch (static device arrays; no allocations) ----------------
__device__ float g_gx[(size_t)TT * BB * 2048];   // precomputed x@Wih^T + b, both dirs (134 MB)
__device__ float g_h[2][2 * BB * HH];            // [buf][dir*8192 + b*256 + k]  (ping-pong h)
__device__ float g_c[2 * BB * HH];               // [dir*8192 + b*256 + k]

__device__ __forceinline__ float sigf(float x) { return 1.0f / (1.0f + expf(-x)); }

// ---------------- Phase 1: GX = cnn_feats @ [Wih_f | Wih_b]^T + bias ----------------
// C[M=16384, N=2048], K=1024. Both operands K-contiguous (NT gemm).
__global__ void __launch_bounds__(256) gemm_gx_kernel(
    const float* __restrict__ A,
    const float* __restrict__ Wf, const float* __restrict__ biasf,
    const float* __restrict__ Wb, const float* __restrict__ biasb)
{
    __shared__ float As[16][132];
    __shared__ float Bs[16][132];
    const int bm = blockIdx.x * 128;
    const int by = blockIdx.y;                       // 0..15 ; <8 -> fwd weights
    const float* W    = (by < 8) ? Wf : Wb;
    const float* bias = (by < 8) ? biasf : biasb;
    const int nloc = (by & 7) * 128;                 // row offset inside that weight matrix
    const int tid = threadIdx.x;
    const int lr = tid >> 2;                         // 0..63
    const int lc = (tid & 3) << 2;                   // 0,4,8,12
    const int tx = tid & 15;
    const int ty = tid >> 4;

    float acc[8][8];
#pragma unroll
    for (int i = 0; i < 8; i++)
#pragma unroll
        for (int j = 0; j < 8; j++) acc[i][j] = 0.0f;

    for (int k0 = 0; k0 < 1024; k0 += 16) {
        float4 a0 = *(const float4*)(A + (size_t)(bm + lr) * 1024 + k0 + lc);
        float4 a1 = *(const float4*)(A + (size_t)(bm + lr + 64) * 1024 + k0 + lc);
        float4 b0 = *(const float4*)(W + (size_t)(nloc + lr) * 1024 + k0 + lc);
        float4 b1 = *(const float4*)(W + (size_t)(nloc + lr + 64) * 1024 + k0 + lc);
        __syncthreads();
        As[lc + 0][lr] = a0.x; As[lc + 1][lr] = a0.y; As[lc + 2][lr] = a0.z; As[lc + 3][lr] = a0.w;
        As[lc + 0][lr + 64] = a1.x; As[lc + 1][lr + 64] = a1.y; As[lc + 2][lr + 64] = a1.z; As[lc + 3][lr + 64] = a1.w;
        Bs[lc + 0][lr] = b0.x; Bs[lc + 1][lr] = b0.y; Bs[lc + 2][lr] = b0.z; Bs[lc + 3][lr] = b0.w;
        Bs[lc + 0][lr + 64] = b1.x; Bs[lc + 1][lr + 64] = b1.y; Bs[lc + 2][lr + 64] = b1.z; Bs[lc + 3][lr + 64] = b1.w;
        __syncthreads();
#pragma unroll
        for (int kk = 0; kk < 16; kk++) {
            float4 fa0 = *(const float4*)&As[kk][ty * 4];
            float4 fa1 = *(const float4*)&As[kk][64 + ty * 4];
            float4 fb0 = *(const float4*)&Bs[kk][tx * 4];
            float4 fb1 = *(const float4*)&Bs[kk][64 + tx * 4];
            float av[8] = {fa0.x, fa0.y, fa0.z, fa0.w, fa1.x, fa1.y, fa1.z, fa1.w};
            float bv[8] = {fb0.x, fb0.y, fb0.z, fb0.w, fb1.x, fb1.y, fb1.z, fb1.w};
#pragma unroll
            for (int i = 0; i < 8; i++)
#pragma unroll
                for (int j = 0; j < 8; j++)
                    acc[i][j] += av[i] * bv[j];
        }
    }

    const int gcolbase = by * 128;
#pragma unroll
    for (int i = 0; i < 8; i++) {
        int rloc = (i < 4) ? (ty * 4 + i) : (64 + ty * 4 + (i - 4));
        float* outp = g_gx + (size_t)(bm + rloc) * 2048 + gcolbase;
        float4 o0, o1;
        o0.x = acc[i][0] + bias[nloc + tx * 4 + 0];
        o0.y = acc[i][1] + bias[nloc + tx * 4 + 1];
        o0.z = acc[i][2] + bias[nloc + tx * 4 + 2];
        o0.w = acc[i][3] + bias[nloc + tx * 4 + 3];
        o1.x = acc[i][4] + bias[nloc + 64 + tx * 4 + 0];
        o1.y = acc[i][5] + bias[nloc + 64 + tx * 4 + 1];
        o1.z = acc[i][6] + bias[nloc + 64 + tx * 4 + 2];
        o1.w = acc[i][7] + bias[nloc + 64 + tx * 4 + 3];
        *(float4*)(outp + tx * 4) = o0;
        *(float4*)(outp + 64 + tx * 4) = o1;
    }
}

// ---------------- Phase 2: one encoder LSTM time-step (both directions) ----------------
// grid = 128 blocks: blocks [0,64) = fwd, [64,128) = bwd; each block owns 4 hidden dims
// (16 gate rows) for all 32 batches. h double-buffered across launches (read hin, write hout).
__global__ void __launch_bounds__(128) enc_step_kernel(
    const float* __restrict__ hin, float* __restrict__ hout, float* __restrict__ cst,
    const float* __restrict__ WhhF, const float* __restrict__ WhhB, int t)
{
    extern __shared__ float sm[];
    float* sH = sm;                 // [32][257]
    float* sW = sm + 32 * 257;      // [16][257]
    float* sG = sW + 16 * 257;      // [16][32]
    const int dir = blockIdx.x >> 6;
    const int h0  = (blockIdx.x & 63) * 4;
    const float* Whh = dir ? WhhB : WhhF;
    const float* h_in = hin + dir * (BB * HH);
    float* h_out = hout + dir * (BB * HH);
    float* cS    = cst  + dir * (BB * HH);
    const int tid = threadIdx.x;

    for (int i = tid; i < BB * HH; i += 128)
        sH[(i >> 8) * 257 + (i & 255)] = h_in[i];
    for (int i = tid; i < 16 * 256; i += 128) {
        int r = i >> 8, k = i & 255;
        int row = (r >> 2) * 256 + h0 + (r & 3);
        sW[r * 257 + k] = Whh[row * 256 + k];
    }
    __syncthreads();

    const int r16 = tid >> 3, bg = tid & 7;
    const int row = (r16 >> 2) * 256 + h0 + (r16 & 3);
    const int teff = dir ? (TT - 1 - t) : t;
    const float* gxp = g_gx + (size_t)teff * BB * 2048 + dir * 1024 + row;
    float a0 = gxp[(size_t)(bg * 4 + 0) * 2048];
    float a1 = gxp[(size_t)(bg * 4 + 1) * 2048];
    float a2 = gxp[(size_t)(bg * 4 + 2) * 2048];
    float a3 = gxp[(size_t)(bg * 4 + 3) * 2048];
    const float* wr  = sW + r16 * 257;
    const float* hp0 = sH + (bg * 4) * 257;
    const float* hp1 = hp0 + 257;
    const float* hp2 = hp0 + 2 * 257;
    const float* hp3 = hp0 + 3 * 257;
#pragma unroll 8
    for (int k = 0; k < 256; k++) {
        float w = wr[k];
        a0 += w * hp0[k];
        a1 += w * hp1[k];
        a2 += w * hp2[k];
        a3 += w * hp3[k];
    }
    sG[r16 * 32 + bg * 4 + 0] = a0;
    sG[r16 * 32 + bg * 4 + 1] = a1;
    sG[r16 * 32 + bg * 4 + 2] = a2;
    sG[r16 * 32 + bg * 4 + 3] = a3;
    __syncthreads();

    {
        const int j = tid >> 5, b = tid & 31;
        float gi = sG[(0  + j) * 32 + b];
        float gf = sG[(4  + j) * 32 + b];
        float gg = sG[(8  + j) * 32 + b];
        float go = sG[(12 + j) * 32 + b];
        const int idx = b * HH + h0 + j;
        float cn = sigf(gf) * cS[idx] + sigf(gi) * tanhf(gg);
        cS[idx] = cn;
        h_out[idx] = sigf(go) * tanhf(cn);
    }
}

// ---------------- Phase 3: one decoder LSTM cell (layer 0 or 1) ----------------
// grid = 64 blocks, 4 hidden dims each. x and h both length-256. Optionally also emits
// the PREVIOUS step's output projection (sX == previous h1) from block 0.
__global__ void __launch_bounds__(128) dec_cell_kernel(
    const float* __restrict__ xin, int zero_x,
    const float* __restrict__ hin, float* __restrict__ hout, float* __restrict__ cst,
    const float* __restrict__ Wih, const float* __restrict__ Whh, const float* __restrict__ bias,
    const float* __restrict__ linW, const float* __restrict__ linb, float* __restrict__ proj_out)
{
    extern __shared__ float sm[];
    float* sX  = sm;                 // [32][257]
    float* sH  = sX  + 32 * 257;     // [32][257]
    float* sWi = sH  + 32 * 257;     // [16][257]
    float* sWh = sWi + 16 * 257;     // [16][257]
    float* sG  = sWh + 16 * 257;     // [16][32]
    const int h0 = blockIdx.x * 4;
    const int tid = threadIdx.x;

    for (int i = tid; i < BB * HH; i += 128) {
        int o = (i >> 8) * 257 + (i & 255);
        sX[o] = zero_x ? 0.0f : xin[i];
        sH[o] = hin[i];
    }
    for (int i = tid; i < 16 * 256; i += 128) {
        int r = i >> 8, k = i & 255;
        int row = (r >> 2) * 256 + h0 + (r & 3);
        sWi[r * 257 + k] = Wih[row * 256 + k];
        sWh[r * 257 + k] = Whh[row * 256 + k];
    }
    __syncthreads();

    const int r16 = tid >> 3, bg = tid & 7;
    const int row = (r16 >> 2) * 256 + h0 + (r16 & 3);
    float bv = bias[row];
    float a0 = bv, a1 = bv, a2 = bv, a3 = bv;
    const float* wi = sWi + r16 * 257;
    const float* wh = sWh + r16 * 257;
    const int bo = bg * 4 * 257;
#pragma unroll 4
    for (int k = 0; k < 256; k++) {
        float vi = wi[k], vh = wh[k];
        a0 += vi * sX[bo + k]           + vh * sH[bo + k];
        a1 += vi * sX[bo + 257 + k]     + vh * sH[bo + 257 + k];
        a2 += vi * sX[bo + 2 * 257 + k] + vh * sH[bo + 2 * 257 + k];
        a3 += vi * sX[bo + 3 * 257 + k] + vh * sH[bo + 3 * 257 + k];
    }
    sG[r16 * 32 + bg * 4 + 0] = a0;
    sG[r16 * 32 + bg * 4 + 1] = a1;
    sG[r16 * 32 + bg * 4 + 2] = a2;
    sG[r16 * 32 + bg * 4 + 3] = a3;
    __syncthreads();

    {
        const int j = tid >> 5, b = tid & 31;
        float gi = sG[(0  + j) * 32 + b];
        float gf = sG[(4  + j) * 32 + b];
        float gg = sG[(8  + j) * 32 + b];
        float go = sG[(12 + j) * 32 + b];
        const int idx = b * HH + h0 + j;
        float cn = sigf(gf) * cst[idx] + sigf(gi) * tanhf(gg);
        cst[idx] = cn;
        hout[idx] = sigf(go) * tanhf(cn);
    }

    // fused projection of the previous step's h1 (staged in sX)
    if (proj_out != nullptr && blockIdx.x == 0 && tid < 96) {
        int b = tid / 3, v = tid - b * 3;
        float acc = linb[v];
        const float* xr = sX + b * 257;
        const float* wv = linW + v * 256;
#pragma unroll 8
        for (int k = 0; k < 256; k++) acc += xr[k] * wv[k];
        proj_out[b * 3 + v] = acc;
    }
}

// final step's projection (no following cell to fold into)
__global__ void proj_kernel(const float* __restrict__ h1, const float* __restrict__ linW,
                            const float* __restrict__ linb, float* __restrict__ y)
{
    int tid = threadIdx.x;
    if (tid >= 96) return;
    int b = tid / 3, v = tid - b * 3;
    float acc = linb[v];
    const float* xr = h1 + b * 256;
    const float* wv = linW + v * 256;
#pragma unroll 8
    for (int k = 0; k < 256; k++) acc += xr[k] * wv[k];
    y[b * 3 + v] = acc;
}

// ---------------- launch ----------------
extern "C" void kernel_launch(void* const* d_in, const int* in_sizes, int n_in,
                              void* d_out, int out_size)
{
    (void)in_sizes; (void)n_in; (void)out_size;
    const float* cnn   = (const float*)d_in[0];
    const float* eWihF = (const float*)d_in[1];
    const float* eWhhF = (const float*)d_in[2];
    const float* ebF   = (const float*)d_in[3];
    const float* eWihB = (const float*)d_in[4];
    const float* eWhhB = (const float*)d_in[5];
    const float* ebB   = (const float*)d_in[6];
    const float* dWih0 = (const float*)d_in[7];
    const float* dWhh0 = (const float*)d_in[8];
    const float* db0   = (const float*)d_in[9];
    const float* dWih1 = (const float*)d_in[10];
    const float* dWhh1 = (const float*)d_in[11];
    const float* db1   = (const float*)d_in[12];
    const float* linW  = (const float*)d_in[13];
    const float* linb  = (const float*)d_in[14];
    float* out = (float*)d_out;

    const int enc_smem = (32 * 257 + 16 * 257 + 16 * 32) * 4;          // 51,392 B
    const int dec_smem = (2 * 32 * 257 + 2 * 16 * 257 + 16 * 32) * 4;  // 100,736 B
    cudaFuncSetAttribute(enc_step_kernel, cudaFuncAttributeMaxDynamicSharedMemorySize, enc_smem);
    cudaFuncSetAttribute(dec_cell_kernel, cudaFuncAttributeMaxDynamicSharedMemorySize, dec_smem);

    float* hbase = nullptr;
    float* cptr  = nullptr;
    cudaGetSymbolAddress((void**)&hbase, g_h);
    cudaGetSymbolAddress((void**)&cptr,  g_c);
    float* hb[2] = { hbase, hbase + 2 * BB * HH };

    // initial encoder state = zeros (read-buffer 0 and c)
    cudaMemsetAsync(hb[0], 0, 2 * BB * HH * sizeof(float));
    cudaMemsetAsync(cptr,  0, 2 * BB * HH * sizeof(float));

    // Phase 1: input-projection GEMM for both directions (+bias folded in)
    gemm_gx_kernel<<<dim3(128, 16), 256>>>(cnn, eWihF, ebF, eWihB, ebB);

    // Phase 2: 512 encoder steps (fwd+bwd in one launch each), h ping-pong
    for (int t = 0; t < TT; t++)
        enc_step_kernel<<<128, 128, enc_smem>>>(hb[t & 1], hb[(t + 1) & 1], cptr, eWhhF, eWhhB, t);

    // After step 511: h final lives in hb[0]; dir0 region = hf (-> decoder h0 init),
    // dir1 region = hb (-> decoder h1 init). c regions likewise. Reuse in place.
    for (int t = 0; t < NSTEP; t++) {
        const float* x = hb[t & 1] + BB * HH;   // previous h1 (zeroed via flag at t==0)
        dec_cell_kernel<<<64, 128, dec_smem>>>(
            x, (t == 0) ? 1 : 0,
            hb[t & 1], hb[(t + 1) & 1], cptr,
            dWih0, dWhh0, db0,
            linW, linb, (t == 0) ? nullptr : (out + (size_t)(t - 1) * 96));
        dec_cell_kernel<<<64, 128, dec_smem>>>(
            hb[(t + 1) & 1], 0,
            hb[t & 1] + BB * HH, hb[(t + 1) & 1] + BB * HH, cptr + BB * HH,
            dWih1, dWhh1, db1,
            linW, linb, nullptr);
    }
    proj_kernel<<<1, 96>>>(hb[NSTEP & 1] + BB * HH, linW, linb, out + (size_t)(NSTEP - 1) * 96);
}

// round 5
// speedup vs baseline: 1.5588x; 1.5588x over previous
#include <cuda_runtime.h>
#include <math.h>
#include <stddef.h>

#define TT 512
#define BB 32
#define HH 256
#define NSTEP 64

// ---------------- scratch (static device arrays; no allocations) ----------------
__device__ float g_gx[(size_t)TT * BB * 2048];   // x@Wih^T + b, both dirs
__device__ float g_h[2][2 * BB * HH];            // encoder h ping-pong [buf][dir*8192 + b*256 + k]
__device__ float g_c[2 * BB * HH];               // encoder final c  [dir*8192 + b*256 + k]
__device__ float g_dh0[2][BB * HH];              // decoder layer0 h ping-pong
__device__ float g_dh1[2][BB * HH];              // decoder layer1 h ping-pong
__device__ unsigned g_cnt[4];                    // barrier arrive counters (self-resetting)
__device__ unsigned g_gen[4];                    // barrier generations (monotonic)

__device__ __forceinline__ float sigf(float x) { return 1.0f / (1.0f + expf(-x)); }

// Software grid barrier. Safe iff all participating blocks are co-resident
// (grid <= 148 blocks -> single wave). Counter self-resets; gen is monotonic,
// so state is valid across graph replays.
__device__ __forceinline__ void gridbar(int id, unsigned nblk) {
    __threadfence();      // order this thread's prior stores before arrival
    __syncthreads();
    if (threadIdx.x == 0) {
        volatile unsigned* genp = (volatile unsigned*)&g_gen[id];
        unsigned my = *genp;
        unsigned a = atomicAdd(&g_cnt[id], 1u);
        if (a == nblk - 1u) {
            atomicExch(&g_cnt[id], 0u);
            __threadfence();
            atomicAdd(&g_gen[id], 1u);
        } else {
            while (*genp == my) { }
        }
        __threadfence();
    }
    __syncthreads();
}

// ---------------- Phase 1: GX = cnn_feats @ [Wih_f | Wih_b]^T + bias ----------------
__global__ void __launch_bounds__(256) gemm_gx_kernel(
    const float* __restrict__ A,
    const float* __restrict__ Wf, const float* __restrict__ biasf,
    const float* __restrict__ Wb, const float* __restrict__ biasb)
{
    __shared__ float As[16][132];
    __shared__ float Bs[16][132];
    const int bm = blockIdx.x * 128;
    const int by = blockIdx.y;
    const float* W    = (by < 8) ? Wf : Wb;
    const float* bias = (by < 8) ? biasf : biasb;
    const int nloc = (by & 7) * 128;
    const int tid = threadIdx.x;
    const int lr = tid >> 2;
    const int lc = (tid & 3) << 2;
    const int tx = tid & 15;
    const int ty = tid >> 4;

    float acc[8][8];
#pragma unroll
    for (int i = 0; i < 8; i++)
#pragma unroll
        for (int j = 0; j < 8; j++) acc[i][j] = 0.0f;

    for (int k0 = 0; k0 < 1024; k0 += 16) {
        float4 a0 = *(const float4*)(A + (size_t)(bm + lr) * 1024 + k0 + lc);
        float4 a1 = *(const float4*)(A + (size_t)(bm + lr + 64) * 1024 + k0 + lc);
        float4 b0 = *(const float4*)(W + (size_t)(nloc + lr) * 1024 + k0 + lc);
        float4 b1 = *(const float4*)(W + (size_t)(nloc + lr + 64) * 1024 + k0 + lc);
        __syncthreads();
        As[lc + 0][lr] = a0.x; As[lc + 1][lr] = a0.y; As[lc + 2][lr] = a0.z; As[lc + 3][lr] = a0.w;
        As[lc + 0][lr + 64] = a1.x; As[lc + 1][lr + 64] = a1.y; As[lc + 2][lr + 64] = a1.z; As[lc + 3][lr + 64] = a1.w;
        Bs[lc + 0][lr] = b0.x; Bs[lc + 1][lr] = b0.y; Bs[lc + 2][lr] = b0.z; Bs[lc + 3][lr] = b0.w;
        Bs[lc + 0][lr + 64] = b1.x; Bs[lc + 1][lr + 64] = b1.y; Bs[lc + 2][lr + 64] = b1.z; Bs[lc + 3][lr + 64] = b1.w;
        __syncthreads();
#pragma unroll
        for (int kk = 0; kk < 16; kk++) {
            float4 fa0 = *(const float4*)&As[kk][ty * 4];
            float4 fa1 = *(const float4*)&As[kk][64 + ty * 4];
            float4 fb0 = *(const float4*)&Bs[kk][tx * 4];
            float4 fb1 = *(const float4*)&Bs[kk][64 + tx * 4];
            float av[8] = {fa0.x, fa0.y, fa0.z, fa0.w, fa1.x, fa1.y, fa1.z, fa1.w};
            float bv[8] = {fb0.x, fb0.y, fb0.z, fb0.w, fb1.x, fb1.y, fb1.z, fb1.w};
#pragma unroll
            for (int i = 0; i < 8; i++)
#pragma unroll
                for (int j = 0; j < 8; j++)
                    acc[i][j] += av[i] * bv[j];
        }
    }

    const int gcolbase = by * 128;
#pragma unroll
    for (int i = 0; i < 8; i++) {
        int rloc = (i < 4) ? (ty * 4 + i) : (64 + ty * 4 + (i - 4));
        float* outp = g_gx + (size_t)(bm + rloc) * 2048 + gcolbase;
        float4 o0, o1;
        o0.x = acc[i][0] + bias[nloc + tx * 4 + 0];
        o0.y = acc[i][1] + bias[nloc + tx * 4 + 1];
        o0.z = acc[i][2] + bias[nloc + tx * 4 + 2];
        o0.w = acc[i][3] + bias[nloc + tx * 4 + 3];
        o1.x = acc[i][4] + bias[nloc + 64 + tx * 4 + 0];
        o1.y = acc[i][5] + bias[nloc + 64 + tx * 4 + 1];
        o1.z = acc[i][6] + bias[nloc + 64 + tx * 4 + 2];
        o1.w = acc[i][7] + bias[nloc + 64 + tx * 4 + 3];
        *(float4*)(outp + tx * 4) = o0;
        *(float4*)(outp + 64 + tx * 4) = o1;
    }
}

// ---------------- Phase 2: persistent encoder (all 512 steps in ONE launch) --------
// 128 blocks x 256 threads. blocks [0,64)=fwd, [64,128)=bwd; block owns 4 hidden dims
// (16 gate rows) resident in smem for the whole recurrence. One grid barrier per step
// per direction; h exchanged via global ping-pong, re-read with __ldcg (L1 bypass).
__global__ void __launch_bounds__(256) enc_persist(
    const float* __restrict__ WhhF, const float* __restrict__ WhhB)
{
    extern __shared__ float sm[];
    float* sW = sm;                  // [16][260]
    float* sH = sW + 16 * 260;       // [32][260]
    float* sG = sH + 32 * 260;       // [16][33]
    float* sC = sG + 16 * 33;        // [128]
    const int dir = blockIdx.x >> 6;
    const int j0  = (blockIdx.x & 63) * 4;
    const int tid = threadIdx.x;
    const float* Whh = dir ? WhhB : WhhF;

    for (int i = tid; i < 16 * 256; i += 256) {
        int r = i >> 8, k = i & 255;
        int row = (r >> 2) * 256 + j0 + (r & 3);
        sW[r * 260 + k] = Whh[row * 256 + k];
    }
    for (int i = tid; i < 32 * 260; i += 256) sH[i] = 0.0f;
    if (tid < 128) sC[tid] = 0.0f;
    __syncthreads();

    const int b  = tid >> 3;
    const int qp = tid & 7;
    const int q0 = qp * 2, q1 = qp * 2 + 1;
    const int row0 = (q0 >> 2) * 256 + j0 + (q0 & 3);
    const int row1 = (q1 >> 2) * 256 + j0 + (q1 & 3);
    const float4* sH4 = (const float4*)sH;
    const float4* sW4 = (const float4*)sW;
    const int hbase4  = b * 65;
    const int w0base4 = q0 * 65, w1base4 = q1 * 65;
    float* hout0 = g_h[0] + dir * (BB * HH);
    float* hout1 = g_h[1] + dir * (BB * HH);

    for (int t = 0; t < TT; t++) {
        const int teff = dir ? (TT - 1 - t) : t;
        const float* gxp = g_gx + (size_t)teff * (BB * 2048) + (size_t)b * 2048 + dir * 1024;
        float gx0 = gxp[row0];                    // issued early, consumed after loop
        float gx1 = gxp[row1];
        float a0 = 0.0f, a1 = 0.0f;
#pragma unroll 8
        for (int k4 = 0; k4 < 64; k4++) {
            float4 hv = sH4[hbase4 + k4];
            float4 w0 = sW4[w0base4 + k4];
            float4 w1 = sW4[w1base4 + k4];
            a0 += w0.x * hv.x + w0.y * hv.y + w0.z * hv.z + w0.w * hv.w;
            a1 += w1.x * hv.x + w1.y * hv.y + w1.z * hv.z + w1.w * hv.w;
        }
        sG[q0 * 33 + b] = a0 + gx0;
        sG[q1 * 33 + b] = a1 + gx1;
        __syncthreads();
        float* hout = (t & 1) ? hout1 : hout0;
        if (tid < 128) {
            const int j = tid >> 5, bb = tid & 31;
            float gi = sG[(0 * 4 + j) * 33 + bb];
            float gf = sG[(1 * 4 + j) * 33 + bb];
            float gg = sG[(2 * 4 + j) * 33 + bb];
            float go = sG[(3 * 4 + j) * 33 + bb];
            float c  = sigf(gf) * sC[tid] + sigf(gi) * tanhf(gg);
            sC[tid] = c;
            hout[bb * 256 + j0 + j] = sigf(go) * tanhf(c);
        }
        gridbar(dir, 64);
        // reload full direction h (32KB) for next step, bypassing L1
        const float4* src = (const float4*)hout;
        float4* dst4 = (float4*)sH;
        for (int i = tid; i < 32 * 64; i += 256) {
            int bb = i >> 6, kk = i & 63;
            dst4[bb * 65 + kk] = __ldcg(src + bb * 64 + kk);
        }
        __syncthreads();
    }
    // dump final c for the decoder (final h already lives in g_h[1])
    if (tid < 128) {
        const int j = tid >> 5, bb = tid & 31;
        g_c[dir * (BB * HH) + bb * 256 + j0 + j] = sC[tid];
    }
}

// ---------------- Phase 3: persistent decoder (all 64 steps in ONE launch) ---------
// 128 blocks x 256 threads; block owns 2 hidden dims of BOTH layers (weights resident
// in smem). Two grid barriers per step. Output projection folded into the next step's
// phase A (sX == previous h1) from block 0; tail projection after the loop.
__global__ void __launch_bounds__(256) dec_persist(
    const float* __restrict__ Wih0, const float* __restrict__ Whh0, const float* __restrict__ b0v,
    const float* __restrict__ Wih1, const float* __restrict__ Whh1, const float* __restrict__ b1v,
    const float* __restrict__ linW, const float* __restrict__ linb,
    float* __restrict__ out)
{
    extern __shared__ float sm[];
    float* sWi0 = sm;                   // [8][260]
    float* sWh0 = sWi0 + 8 * 260;
    float* sWi1 = sWh0 + 8 * 260;
    float* sWh1 = sWi1 + 8 * 260;
    float* sX   = sWh1 + 8 * 260;       // [32][260]
    float* sH   = sX + 32 * 260;        // [32][260]
    float* sG   = sH + 32 * 260;        // [8][33]
    float* sC   = sG + 8 * 33;          // [128]: c0 in [0,64), c1 in [64,128)
    const int tid = threadIdx.x;
    const int j0 = blockIdx.x * 2;

    for (int i = tid; i < 8 * 256; i += 256) {
        int r = i >> 8, k = i & 255;
        int row = (r >> 1) * 256 + j0 + (r & 1);
        sWi0[r * 260 + k] = Wih0[row * 256 + k];
        sWh0[r * 260 + k] = Whh0[row * 256 + k];
        sWi1[r * 260 + k] = Wih1[row * 256 + k];
        sWh1[r * 260 + k] = Whh1[row * 256 + k];
    }
    if (tid < 64) {
        int d = tid >> 5, bb = tid & 31;
        sC[tid]      = g_c[bb * 256 + j0 + d];             // cf -> c0 init
        sC[64 + tid] = g_c[BB * HH + bb * 256 + j0 + d];   // cb -> c1 init
    }
    __syncthreads();

    const float* hf = g_h[1];            // encoder final h, dir 0 (TT even -> buf 1)
    const float* hb = g_h[1] + BB * HH;  // encoder final h, dir 1
    const int b = tid >> 3, q = tid & 7;
    const int row = (q >> 1) * 256 + j0 + (q & 1);
    const float bias0 = b0v[row], bias1 = b1v[row];
    const float4* sX4 = (const float4*)sX;
    const float4* sH4 = (const float4*)sH;

    for (int t = 0; t < NSTEP; t++) {
        // ---- phase A: layer 0  (x = prev h1, h = prev h0) ----
        {
            float4* dX = (float4*)sX;
            float4* dH = (float4*)sH;
            const float4* srcX = (t == 0) ? (const float4*)0 : (const float4*)g_dh1[(t + 1) & 1];
            const float4* srcH = (t == 0) ? (const float4*)hf : (const float4*)g_dh0[(t + 1) & 1];
            for (int i = tid; i < 32 * 64; i += 256) {
                int bb = i >> 6, kk = i & 63;
                dX[bb * 65 + kk] = srcX ? __ldcg(srcX + bb * 64 + kk) : make_float4(0.f, 0.f, 0.f, 0.f);
                dH[bb * 65 + kk] = __ldcg(srcH + bb * 64 + kk);
            }
            __syncthreads();
            if (t > 0 && blockIdx.x == 0 && tid < 96) {      // y_{t-1} from sX = h1_{t-1}
                int pb = tid / 3, pv = tid - pb * 3;
                float acc = linb[pv];
                const float* xr = sX + pb * 260;
                const float* wv = linW + pv * 256;
#pragma unroll 8
                for (int k = 0; k < 256; k++) acc += xr[k] * wv[k];
                out[(size_t)(t - 1) * 96 + pb * 3 + pv] = acc;
            }
            float a = 0.0f;
            const float4* wi4 = (const float4*)sWi0 + q * 65;
            const float4* wh4 = (const float4*)sWh0 + q * 65;
#pragma unroll 8
            for (int k4 = 0; k4 < 64; k4++) {
                float4 xv = sX4[b * 65 + k4], hv = sH4[b * 65 + k4];
                float4 wi = wi4[k4], wh = wh4[k4];
                a += wi.x * xv.x + wi.y * xv.y + wi.z * xv.z + wi.w * xv.w;
                a += wh.x * hv.x + wh.y * hv.y + wh.z * hv.z + wh.w * hv.w;
            }
            sG[q * 33 + b] = a + bias0;
            __syncthreads();
            if (tid < 64) {
                int d = tid >> 5, bb = tid & 31;
                float gi = sG[(0 * 2 + d) * 33 + bb];
                float gf = sG[(1 * 2 + d) * 33 + bb];
                float gg = sG[(2 * 2 + d) * 33 + bb];
                float go = sG[(3 * 2 + d) * 33 + bb];
                float c = sigf(gf) * sC[tid] + sigf(gi) * tanhf(gg);
                sC[tid] = c;
                g_dh0[t & 1][bb * 256 + j0 + d] = sigf(go) * tanhf(c);
            }
            gridbar(2, 128);
        }
        // ---- phase B: layer 1  (x = new h0, h = prev h1) ----
        {
            float4* dX = (float4*)sX;
            float4* dH = (float4*)sH;
            const float4* srcX = (const float4*)g_dh0[t & 1];
            const float4* srcH = (t == 0) ? (const float4*)hb : (const float4*)g_dh1[(t + 1) & 1];
            for (int i = tid; i < 32 * 64; i += 256) {
                int bb = i >> 6, kk = i & 63;
                dX[bb * 65 + kk] = __ldcg(srcX + bb * 64 + kk);
                dH[bb * 65 + kk] = __ldcg(srcH + bb * 64 + kk);
            }
            __syncthreads();
            float a = 0.0f;
            const float4* wi4 = (const float4*)sWi1 + q * 65;
            const float4* wh4 = (const float4*)sWh1 + q * 65;
#pragma unroll 8
            for (int k4 = 0; k4 < 64; k4++) {
                float4 xv = sX4[b * 65 + k4], hv = sH4[b * 65 + k4];
                float4 wi = wi4[k4], wh = wh4[k4];
                a += wi.x * xv.x + wi.y * xv.y + wi.z * xv.z + wi.w * xv.w;
                a += wh.x * hv.x + wh.y * hv.y + wh.z * hv.z + wh.w * hv.w;
            }
            sG[q * 33 + b] = a + bias1;
            __syncthreads();
            if (tid < 64) {
                int d = tid >> 5, bb = tid & 31;
                float gi = sG[(0 * 2 + d) * 33 + bb];
                float gf = sG[(1 * 2 + d) * 33 + bb];
                float gg = sG[(2 * 2 + d) * 33 + bb];
                float go = sG[(3 * 2 + d) * 33 + bb];
                float c = sigf(gf) * sC[64 + tid] + sigf(gi) * tanhf(gg);
                sC[64 + tid] = c;
                g_dh1[t & 1][bb * 256 + j0 + d] = sigf(go) * tanhf(c);
            }
            gridbar(2, 128);
        }
    }
    // tail projection: y_{63} from final h1 (buffer (NSTEP-1)&1 = 1)
    if (blockIdx.x == 0 && tid < 96) {
        int pb = tid / 3, pv = tid - pb * 3;
        float acc = linb[pv];
        const float* xr = g_dh1[(NSTEP - 1) & 1] + pb * 256;
        const float* wv = linW + pv * 256;
#pragma unroll 8
        for (int k = 0; k < 256; k++) acc += __ldcg(xr + k) * wv[k];
        out[(size_t)(NSTEP - 1) * 96 + pb * 3 + pv] = acc;
    }
}

// ---------------- launch ----------------
extern "C" void kernel_launch(void* const* d_in, const int* in_sizes, int n_in,
                              void* d_out, int out_size)
{
    (void)in_sizes; (void)n_in; (void)out_size;
    const float* cnn   = (const float*)d_in[0];
    const float* eWihF = (const float*)d_in[1];
    const float* eWhhF = (const float*)d_in[2];
    const float* ebF   = (const float*)d_in[3];
    const float* eWihB = (const float*)d_in[4];
    const float* eWhhB = (const float*)d_in[5];
    const float* ebB   = (const float*)d_in[6];
    const float* dWih0 = (const float*)d_in[7];
    const float* dWhh0 = (const float*)d_in[8];
    const float* db0   = (const float*)d_in[9];
    const float* dWih1 = (const float*)d_in[10];
    const float* dWhh1 = (const float*)d_in[11];
    const float* db1   = (const float*)d_in[12];
    const float* linW  = (const float*)d_in[13];
    const float* linb  = (const float*)d_in[14];
    float* out = (float*)d_out;

    const int enc_smem = (16 * 260 + 32 * 260 + 16 * 33 + 128) * 4;            // 52,544 B
    const int dec_smem = (4 * 8 * 260 + 2 * 32 * 260 + 8 * 33 + 128) * 4;      // 101,408 B
    cudaFuncSetAttribute(enc_persist, cudaFuncAttributeMaxDynamicSharedMemorySize, enc_smem);
    cudaFuncSetAttribute(dec_persist, cudaFuncAttributeMaxDynamicSharedMemorySize, dec_smem);

    // Phase 1: input-projection GEMM (both directions, bias folded)
    gemm_gx_kernel<<<dim3(128, 16), 256>>>(cnn, eWihF, ebF, eWihB, ebB);

    // Phase 2: entire encoder recurrence in one persistent launch
    enc_persist<<<128, 256, enc_smem>>>(eWhhF, eWhhB);

    // Phase 3: entire decoder + projections in one persistent launch
    dec_persist<<<128, 256, dec_smem>>>(dWih0, dWhh0, db0, dWih1, dWhh1, db1,
                                        linW, linb, out);
}

// round 10
// speedup vs baseline: 1.7395x; 1.1159x over previous
#include <cuda_runtime.h>
#include <cuda_bf16.h>
#include <math.h>
#include <stddef.h>
#include <stdint.h>

#define TT 512
#define BB 32
#define HH 256
#define NSTEP 64

// ---------------- scratch (static device arrays; no allocations) ----------------
__device__ float g_gx[(size_t)TT * BB * 2048];                     // x@Wih^T + b, both dirs
__device__ __align__(16) __nv_bfloat16 g_A2[(size_t)16384 * 3072]; // [Ahi | Ahi | Alo]
__device__ __align__(16) __nv_bfloat16 g_W2[(size_t)2048 * 3072];  // [Whi | Wlo | Whi]
__device__ float g_h[2][2 * BB * HH];
__device__ float g_c[2 * BB * HH];
__device__ float g_dh0[2][BB * HH];
__device__ float g_dh1[2][BB * HH];
__device__ unsigned g_cnt[4];
__device__ unsigned g_gen[4];

__device__ __forceinline__ float sigf(float x) { return 1.0f / (1.0f + expf(-x)); }

__device__ __forceinline__ uint32_t smem_u32(const void* p) {
    return (uint32_t)__cvta_generic_to_shared(p);
}
#define SMEM_SWIZZLE_128B(b) ((b) ^ (((b) >> 3) & 0x70))

// Software grid barrier (all participating blocks co-resident; grid <= 148).
__device__ __forceinline__ void gridbar(int id, unsigned nblk) {
    __threadfence();
    __syncthreads();
    if (threadIdx.x == 0) {
        volatile unsigned* genp = (volatile unsigned*)&g_gen[id];
        unsigned my = *genp;
        unsigned a = atomicAdd(&g_cnt[id], 1u);
        if (a == nblk - 1u) {
            atomicExch(&g_cnt[id], 0u);
            __threadfence();
            atomicAdd(&g_gen[id], 1u);
        } else {
            while (*genp == my) { }
        }
        __threadfence();
    }
    __syncthreads();
}

// ---------------- Phase 0: fp32 -> bf16 hi/lo split ----------------
__device__ __forceinline__ void split4(float4 v, uint2& hp, uint2& lp) {
    float f[4] = {v.x, v.y, v.z, v.w};
    unsigned short hu[4], lu[4];
#pragma unroll
    for (int j = 0; j < 4; j++) {
        __nv_bfloat16 h = __float2bfloat16(f[j]);
        float hf = __bfloat162float(h);
        __nv_bfloat16 l = __float2bfloat16(f[j] - hf);   // x - hi exact in fp32
        hu[j] = *(unsigned short*)&h;
        lu[j] = *(unsigned short*)&l;
    }
    hp.x = hu[0] | ((unsigned)hu[1] << 16); hp.y = hu[2] | ((unsigned)hu[3] << 16);
    lp.x = lu[0] | ((unsigned)lu[1] << 16); lp.y = lu[2] | ((unsigned)lu[3] << 16);
}

__global__ void __launch_bounds__(256) conv_a(const float* __restrict__ X) {
    size_t i = (size_t)blockIdx.x * 256 + threadIdx.x;   // float4 index
    float4 v = ((const float4*)X)[i];
    size_t e = i << 2;
    size_t m = e >> 10;
    int k = (int)(e & 1023);
    uint2 hp, lp;
    split4(v, hp, lp);
    __nv_bfloat16* rp = g_A2 + m * 3072 + k;
    *(uint2*)(rp)        = hp;   // seg0: hi
    *(uint2*)(rp + 1024) = hp;   // seg1: hi
    *(uint2*)(rp + 2048) = lp;   // seg2: lo
}

__global__ void __launch_bounds__(256) conv_w(const float* __restrict__ Wf, const float* __restrict__ Wb) {
    size_t i = (size_t)blockIdx.x * 256 + threadIdx.x;
    size_t e = i << 2;
    size_t n = e >> 10;
    int k = (int)(e & 1023);
    const float* src = (n < 1024) ? (Wf + n * 1024 + k) : (Wb + (n - 1024) * 1024 + k);
    float4 v = *(const float4*)src;
    uint2 hp, lp;
    split4(v, hp, lp);
    __nv_bfloat16* rp = g_W2 + n * 3072 + k;
    *(uint2*)(rp)        = hp;   // seg0: hi
    *(uint2*)(rp + 1024) = lp;   // seg1: lo
    *(uint2*)(rp + 2048) = hp;   // seg2: hi
}

// ---------------- Phase 1: HMMA bf16 GEMM  g_gx = A2 @ W2^T + bias ----------------
// C[16384, 2048], K=3072. Block tile 128x256, warp tile 64x64 (2x4 warps),
// mma.sync m16n8k16 bf16->fp32, K-chunk 64 (SW128 rows), cp.async double buffer.
#define SM_A0 0
#define SM_A1 16384
#define SM_B0 32768
#define SM_B1 65536
#define SM_TOT 98304
#define NC 48

__device__ __forceinline__ void cp16(uint32_t dst, const void* src) {
    asm volatile("cp.async.cg.shared.global [%0], [%1], 16;" :: "r"(dst), "l"(src));
}

__global__ void __launch_bounds__(256) gemm_mma(const float* __restrict__ biasf,
                                                const float* __restrict__ biasb)
{
    extern __shared__ char smem[];
    const uint32_t sb = smem_u32(smem);
    const int tid = threadIdx.x;
    const int warp = tid >> 5, lane = tid & 31;
    const int bm = blockIdx.x * 128;
    const int bn = blockIdx.y * 256;
    const int warp_m = (warp & 1) * 64;
    const int warp_n = (warp >> 1) * 64;

    const __nv_bfloat16* Ab = g_A2 + (size_t)bm * 3072;
    const __nv_bfloat16* Bb = g_W2 + (size_t)bn * 3072;

    float acc[4][8][4];
#pragma unroll
    for (int im = 0; im < 4; im++)
#pragma unroll
        for (int in = 0; in < 8; in++)
#pragma unroll
            for (int q = 0; q < 4; q++) acc[im][in][q] = 0.0f;

    // per-thread load slots: A = 4x16B (128 rows x 8 chunks), B = 8x16B (256 rows x 8 chunks)
    const int arow[4] = { (tid + 0) >> 3, (tid + 256) >> 3, (tid + 512) >> 3, (tid + 768) >> 3 };
    const int aj = tid & 7;

    auto load_stage = [&](int c, int buf) {
        const int kb = c * 64;
        const uint32_t dA = sb + (buf ? SM_A1 : SM_A0);
        const uint32_t dB = sb + (buf ? SM_B1 : SM_B0);
#pragma unroll
        for (int i = 0; i < 4; i++) {
            int row = arow[i];
            cp16(dA + SMEM_SWIZZLE_128B(row * 128 + aj * 16),
                 Ab + (size_t)row * 3072 + kb + aj * 8);
        }
#pragma unroll
        for (int i = 0; i < 8; i++) {
            int idx = tid + i * 256;
            int row = idx >> 3, j = idx & 7;
            cp16(dB + SMEM_SWIZZLE_128B(row * 128 + j * 16),
                 Bb + (size_t)row * 3072 + kb + j * 8);
        }
        asm volatile("cp.async.commit_group;" ::: "memory");
    };

    load_stage(0, 0);

    for (int c = 0; c < NC; c++) {
        const int cur = c & 1;
        if (c + 1 < NC) {
            load_stage(c + 1, cur ^ 1);
            asm volatile("cp.async.wait_group 1;" ::: "memory");
        } else {
            asm volatile("cp.async.wait_group 0;" ::: "memory");
        }
        __syncthreads();

        const uint32_t aBase = sb + (cur ? SM_A1 : SM_A0);
        const uint32_t bBase = sb + (cur ? SM_B1 : SM_B0);
#pragma unroll
        for (int ks = 0; ks < 4; ks++) {
            uint32_t af[4][4];
#pragma unroll
            for (int im = 0; im < 4; im++) {
                int row = warp_m + im * 16 + (lane & 15);
                uint32_t addr = aBase + SMEM_SWIZZLE_128B(row * 128 + ks * 32 + ((lane >> 4) << 4));
                asm volatile("ldmatrix.sync.aligned.m8n8.x4.shared.b16 {%0,%1,%2,%3}, [%4];"
                    : "=r"(af[im][0]), "=r"(af[im][1]), "=r"(af[im][2]), "=r"(af[im][3])
                    : "r"(addr));
            }
            uint32_t bf[8][2];
#pragma unroll
            for (int ib = 0; ib < 4; ib++) {
                int row = warp_n + ib * 16 + (lane & 7) + (((lane >> 4) & 1) << 3);
                uint32_t addr = bBase + SMEM_SWIZZLE_128B(row * 128 + ks * 32 + (((lane >> 3) & 1) << 4));
                asm volatile("ldmatrix.sync.aligned.m8n8.x4.shared.b16 {%0,%1,%2,%3}, [%4];"
                    : "=r"(bf[2 * ib][0]), "=r"(bf[2 * ib][1]),
                      "=r"(bf[2 * ib + 1][0]), "=r"(bf[2 * ib + 1][1])
                    : "r"(addr));
            }
#pragma unroll
            for (int im = 0; im < 4; im++)
#pragma unroll
                for (int in = 0; in < 8; in++) {
                    asm volatile(
                        "mma.sync.aligned.m16n8k16.row.col.f32.bf16.bf16.f32 "
                        "{%0,%1,%2,%3}, {%4,%5,%6,%7}, {%8,%9}, {%0,%1,%2,%3};"
                        : "+f"(acc[im][in][0]), "+f"(acc[im][in][1]),
                          "+f"(acc[im][in][2]), "+f"(acc[im][in][3])
                        : "r"(af[im][0]), "r"(af[im][1]), "r"(af[im][2]), "r"(af[im][3]),
                          "r"(bf[in][0]), "r"(bf[in][1]));
                }
        }
        __syncthreads();
    }

    // epilogue: +bias, write fp32 to g_gx
    const float* bp = (bn < 1024) ? (biasf + bn) : (biasb + (bn - 1024));
#pragma unroll
    for (int im = 0; im < 4; im++) {
        const int r0 = bm + warp_m + im * 16 + (lane >> 2);
#pragma unroll
        for (int in = 0; in < 8; in++) {
            const int cl = warp_n + in * 8 + (lane & 3) * 2;
            float bx = __ldg(bp + cl), by = __ldg(bp + cl + 1);
            float2 v0 = { acc[im][in][0] + bx, acc[im][in][1] + by };
            float2 v1 = { acc[im][in][2] + bx, acc[im][in][3] + by };
            *(float2*)(g_gx + (size_t)r0 * 2048 + bn + cl) = v0;
            *(float2*)(g_gx + (size_t)(r0 + 8) * 2048 + bn + cl) = v1;
        }
    }
}

// ---------------- Phase 2: persistent encoder (unchanged, passing) ----------------
__global__ void __launch_bounds__(256) enc_persist(
    const float* __restrict__ WhhF, const float* __restrict__ WhhB)
{
    extern __shared__ float sm[];
    float* sW = sm;
    float* sH = sW + 16 * 260;
    float* sG = sH + 32 * 260;
    float* sC = sG + 16 * 33;
    const int dir = blockIdx.x >> 6;
    const int j0  = (blockIdx.x & 63) * 4;
    const int tid = threadIdx.x;
    const float* Whh = dir ? WhhB : WhhF;

    for (int i = tid; i < 16 * 256; i += 256) {
        int r = i >> 8, k = i & 255;
        int row = (r >> 2) * 256 + j0 + (r & 3);
        sW[r * 260 + k] = Whh[row * 256 + k];
    }
    for (int i = tid; i < 32 * 260; i += 256) sH[i] = 0.0f;
    if (tid < 128) sC[tid] = 0.0f;
    __syncthreads();

    const int b  = tid >> 3;
    const int qp = tid & 7;
    const int q0 = qp * 2, q1 = qp * 2 + 1;
    const int row0 = (q0 >> 2) * 256 + j0 + (q0 & 3);
    const int row1 = (q1 >> 2) * 256 + j0 + (q1 & 3);
    const float4* sH4 = (const float4*)sH;
    const float4* sW4 = (const float4*)sW;
    const int hbase4  = b * 65;
    const int w0base4 = q0 * 65, w1base4 = q1 * 65;
    float* hout0 = g_h[0] + dir * (BB * HH);
    float* hout1 = g_h[1] + dir * (BB * HH);

    for (int t = 0; t < TT; t++) {
        const int teff = dir ? (TT - 1 - t) : t;
        const float* gxp = g_gx + (size_t)teff * (BB * 2048) + (size_t)b * 2048 + dir * 1024;
        float gx0 = gxp[row0];
        float gx1 = gxp[row1];
        float a0 = 0.0f, a1 = 0.0f;
#pragma unroll 8
        for (int k4 = 0; k4 < 64; k4++) {
            float4 hv = sH4[hbase4 + k4];
            float4 w0 = sW4[w0base4 + k4];
            float4 w1 = sW4[w1base4 + k4];
            a0 += w0.x * hv.x + w0.y * hv.y + w0.z * hv.z + w0.w * hv.w;
            a1 += w1.x * hv.x + w1.y * hv.y + w1.z * hv.z + w1.w * hv.w;
        }
        sG[q0 * 33 + b] = a0 + gx0;
        sG[q1 * 33 + b] = a1 + gx1;
        __syncthreads();
        float* hout = (t & 1) ? hout1 : hout0;
        if (tid < 128) {
            const int j = tid >> 5, bb = tid & 31;
            float gi = sG[(0 * 4 + j) * 33 + bb];
            float gf = sG[(1 * 4 + j) * 33 + bb];
            float gg = sG[(2 * 4 + j) * 33 + bb];
            float go = sG[(3 * 4 + j) * 33 + bb];
            float c  = sigf(gf) * sC[tid] + sigf(gi) * tanhf(gg);
            sC[tid] = c;
            hout[bb * 256 + j0 + j] = sigf(go) * tanhf(c);
        }
        gridbar(dir, 64);
        const float4* src = (const float4*)hout;
        float4* dst4 = (float4*)sH;
        for (int i = tid; i < 32 * 64; i += 256) {
            int bb = i >> 6, kk = i & 63;
            dst4[bb * 65 + kk] = __ldcg(src + bb * 64 + kk);
        }
        __syncthreads();
    }
    if (tid < 128) {
        const int j = tid >> 5, bb = tid & 31;
        g_c[dir * (BB * HH) + bb * 256 + j0 + j] = sC[tid];
    }
}

// ---------------- Phase 3: persistent decoder (unchanged, passing) ----------------
__global__ void __launch_bounds__(256) dec_persist(
    const float* __restrict__ Wih0, const float* __restrict__ Whh0, const float* __restrict__ b0v,
    const float* __restrict__ Wih1, const float* __restrict__ Whh1, const float* __restrict__ b1v,
    const float* __restrict__ linW, const float* __restrict__ linb,
    float* __restrict__ out)
{
    extern __shared__ float sm[];
    float* sWi0 = sm;
    float* sWh0 = sWi0 + 8 * 260;
    float* sWi1 = sWh0 + 8 * 260;
    float* sWh1 = sWi1 + 8 * 260;
    float* sX   = sWh1 + 8 * 260;
    float* sH   = sX + 32 * 260;
    float* sG   = sH + 32 * 260;
    float* sC   = sG + 8 * 33;
    const int tid = threadIdx.x;
    const int j0 = blockIdx.x * 2;

    for (int i = tid; i < 8 * 256; i += 256) {
        int r = i >> 8, k = i & 255;
        int row = (r >> 1) * 256 + j0 + (r & 1);
        sWi0[r * 260 + k] = Wih0[row * 256 + k];
        sWh0[r * 260 + k] = Whh0[row * 256 + k];
        sWi1[r * 260 + k] = Wih1[row * 256 + k];
        sWh1[r * 260 + k] = Whh1[row * 256 + k];
    }
    if (tid < 64) {
        int d = tid >> 5, bb = tid & 31;
        sC[tid]      = g_c[bb * 256 + j0 + d];
        sC[64 + tid] = g_c[BB * HH + bb * 256 + j0 + d];
    }
    __syncthreads();

    const float* hf = g_h[1];
    const float* hb = g_h[1] + BB * HH;
    const int b = tid >> 3, q = tid & 7;
    const int row = (q >> 1) * 256 + j0 + (q & 1);
    const float bias0 = b0v[row], bias1 = b1v[row];
    const float4* sX4 = (const float4*)sX;
    const float4* sH4 = (const float4*)sH;

    for (int t = 0; t < NSTEP; t++) {
        {
            float4* dX = (float4*)sX;
            float4* dH = (float4*)sH;
            const float4* srcX = (t == 0) ? (const float4*)0 : (const float4*)g_dh1[(t + 1) & 1];
            const float4* srcH = (t == 0) ? (const float4*)hf : (const float4*)g_dh0[(t + 1) & 1];
            for (int i = tid; i < 32 * 64; i += 256) {
                int bb = i >> 6, kk = i & 63;
                dX[bb * 65 + kk] = srcX ? __ldcg(srcX + bb * 64 + kk) : make_float4(0.f, 0.f, 0.f, 0.f);
                dH[bb * 65 + kk] = __ldcg(srcH + bb * 64 + kk);
            }
            __syncthreads();
            if (t > 0 && blockIdx.x == 0 && tid < 96) {
                int pb = tid / 3, pv = tid - pb * 3;
                float acc = linb[pv];
                const float* xr = sX + pb * 260;
                const float* wv = linW + pv * 256;
#pragma unroll 8
                for (int k = 0; k < 256; k++) acc += xr[k] * wv[k];
                out[(size_t)(t - 1) * 96 + pb * 3 + pv] = acc;
            }
            float a = 0.0f;
            const float4* wi4 = (const float4*)sWi0 + q * 65;
            const float4* wh4 = (const float4*)sWh0 + q * 65;
#pragma unroll 8
            for (int k4 = 0; k4 < 64; k4++) {
                float4 xv = sX4[b * 65 + k4], hv = sH4[b * 65 + k4];
                float4 wi = wi4[k4], wh = wh4[k4];
                a += wi.x * xv.x + wi.y * xv.y + wi.z * xv.z + wi.w * xv.w;
                a += wh.x * hv.x + wh.y * hv.y + wh.z * hv.z + wh.w * hv.w;
            }
            sG[q * 33 + b] = a + bias0;
            __syncthreads();
            if (tid < 64) {
                int d = tid >> 5, bb = tid & 31;
                float gi = sG[(0 * 2 + d) * 33 + bb];
                float gf = sG[(1 * 2 + d) * 33 + bb];
                float gg = sG[(2 * 2 + d) * 33 + bb];
                float go = sG[(3 * 2 + d) * 33 + bb];
                float c = sigf(gf) * sC[tid] + sigf(gi) * tanhf(gg);
                sC[tid] = c;
                g_dh0[t & 1][bb * 256 + j0 + d] = sigf(go) * tanhf(c);
            }
            gridbar(2, 128);
        }
        {
            float4* dX = (float4*)sX;
            float4* dH = (float4*)sH;
            const float4* srcX = (const float4*)g_dh0[t & 1];
            const float4* srcH = (t == 0) ? (const float4*)hb : (const float4*)g_dh1[(t + 1) & 1];
            for (int i = tid; i < 32 * 64; i += 256) {
                int bb = i >> 6, kk = i & 63;
                dX[bb * 65 + kk] = __ldcg(srcX + bb * 64 + kk);
                dH[bb * 65 + kk] = __ldcg(srcH + bb * 64 + kk);
            }
            __syncthreads();
            float a = 0.0f;
            const float4* wi4 = (const float4*)sWi1 + q * 65;
            const float4* wh4 = (const float4*)sWh1 + q * 65;
#pragma unroll 8
            for (int k4 = 0; k4 < 64; k4++) {
                float4 xv = sX4[b * 65 + k4], hv = sH4[b * 65 + k4];
                float4 wi = wi4[k4], wh = wh4[k4];
                a += wi.x * xv.x + wi.y * xv.y + wi.z * xv.z + wi.w * xv.w;
                a += wh.x * hv.x + wh.y * hv.y + wh.z * hv.z + wh.w * hv.w;
            }
            sG[q * 33 + b] = a + bias1;
            __syncthreads();
            if (tid < 64) {
                int d = tid >> 5, bb = tid & 31;
                float gi = sG[(0 * 2 + d) * 33 + bb];
                float gf = sG[(1 * 2 + d) * 33 + bb];
                float gg = sG[(2 * 2 + d) * 33 + bb];
                float go = sG[(3 * 2 + d) * 33 + bb];
                float c = sigf(gf) * sC[64 + tid] + sigf(gi) * tanhf(gg);
                sC[64 + tid] = c;
                g_dh1[t & 1][bb * 256 + j0 + d] = sigf(go) * tanhf(c);
            }
            gridbar(2, 128);
        }
    }
    if (blockIdx.x == 0 && tid < 96) {
        int pb = tid / 3, pv = tid - pb * 3;
        float acc = linb[pv];
        const float* xr = g_dh1[(NSTEP - 1) & 1] + pb * 256;
        const float* wv = linW + pv * 256;
#pragma unroll 8
        for (int k = 0; k < 256; k++) acc += __ldcg(xr + k) * wv[k];
        out[(size_t)(NSTEP - 1) * 96 + pb * 3 + pv] = acc;
    }
}

// ---------------- launch ----------------
extern "C" void kernel_launch(void* const* d_in, const int* in_sizes, int n_in,
                              void* d_out, int out_size)
{
    (void)in_sizes; (void)n_in; (void)out_size;
    const float* cnn   = (const float*)d_in[0];
    const float* eWihF = (const float*)d_in[1];
    const float* eWhhF = (const float*)d_in[2];
    const float* ebF   = (const float*)d_in[3];
    const float* eWihB = (const float*)d_in[4];
    const float* eWhhB = (const float*)d_in[5];
    const float* ebB   = (const float*)d_in[6];
    const float* dWih0 = (const float*)d_in[7];
    const float* dWhh0 = (const float*)d_in[8];
    const float* db0   = (const float*)d_in[9];
    const float* dWih1 = (const float*)d_in[10];
    const float* dWhh1 = (const float*)d_in[11];
    const float* db1   = (const float*)d_in[12];
    const float* linW  = (const float*)d_in[13];
    const float* linb  = (const float*)d_in[14];
    float* out = (float*)d_out;

    const int enc_smem = (16 * 260 + 32 * 260 + 16 * 33 + 128) * 4;
    const int dec_smem = (4 * 8 * 260 + 2 * 32 * 260 + 8 * 33 + 128) * 4;
    cudaFuncSetAttribute(gemm_mma,    cudaFuncAttributeMaxDynamicSharedMemorySize, SM_TOT);
    cudaFuncSetAttribute(enc_persist, cudaFuncAttributeMaxDynamicSharedMemorySize, enc_smem);
    cudaFuncSetAttribute(dec_persist, cudaFuncAttributeMaxDynamicSharedMemorySize, dec_smem);

    // Phase 0: bf16 hi/lo splits of activations and both Wih matrices
    conv_a<<<16384, 256>>>(cnn);
    conv_w<<<2048, 256>>>(eWihF, eWihB);

    // Phase 1: HMMA bf16 3-term input-projection GEMM (bias folded)
    gemm_mma<<<dim3(128, 8), 256, SM_TOT>>>(ebF, ebB);

    // Phase 2: entire encoder recurrence in one persistent launch
    enc_persist<<<128, 256, enc_smem>>>(eWhhF, eWhhB);

    // Phase 3: entire decoder + projections in one persistent launch
    dec_persist<<<128, 256, dec_smem>>>(dWih0, dWhh0, db0, dWih1, dWhh1, db1,
                                        linW, linb, out);
}